// round 8
// baseline (speedup 1.0000x reference)
#include <cuda_runtime.h>
#include <math.h>
#include <stdint.h>

#define B_  16
#define N_  307
#define T_  12
#define C_  64
#define TC_ 768
#define NH_ 32
#define DK_ 24
#define DV_ 8
#define NORM_ 0.2041241452319315f

__device__ __forceinline__ float sg(float x){ return 1.f/(1.f+__expf(-x)); }

// ---------------- scratch offsets (floats) ----------------
constexpr long ELT = (long)B_*N_*T_*C_;   // 3772416
constexpr long G4  = 4L*B_*N_*C_;         // 1257472
constexpr long O_A    = 0;
constexpr long O_RS   = O_A    + 94272;
constexpr long O_W    = O_RS   + 512;
constexpr long O_EM   = O_W    + 5*4096;
constexpr long O_U3   = O_EM   + 58944;
constexpr long O_U4   = O_U3   + 58944;
constexpr long O_P    = O_U4   + 58944;
constexpr long O_S3   = O_P    + 58944;
constexpr long O_S4   = O_S3   + 256;
constexpr long O_C34  = O_S4   + 256;
constexpr long O_ATTE = O_C34  + 2304;
constexpr long O_COEFE= O_ATTE + (long)B_*N_*144;
constexpr long O_BASE = O_COEFE+ 58944;
constexpr long O_R    = O_BASE + 12288;
constexpr long O_G0   = O_R    + 147456;
constexpr long O_SN   = O_G0   + 64;
constexpr long O_AL   = O_SN   + ELT;
constexpr long O_AR   = O_AL   + ELT;
constexpr long O_ATTN = O_AR   + ELT;
constexpr long O_XW   = O_ATTN + (long)B_*C_*144;
constexpr long O_X0N  = O_XW   + ELT;
constexpr long O_Q    = O_X0N  + ELT;
constexpr long O_K    = O_Q    + ELT;
constexpr long O_V    = O_K    + ELT;
constexpr long O_Z0   = O_V    + G4;
constexpr long O_Z    = O_Z0   + G4;
constexpr long O_SZ   = O_Z    + G4;
constexpr long O_ZW   = O_SZ   + G4;
constexpr long O_ATT3 = O_ZW   + G4;
constexpr long O_X1S  = O_ATT3 + 4096;
constexpr long O_X1C  = O_X1S  + ELT;
constexpr long O_XG   = O_X1C  + ELT;
constexpr long O_XL   = O_XG   + ELT;
constexpr long O_XE   = O_XL   + ELT;
constexpr long O_Z1   = O_XE   + ELT;
constexpr long O_T1   = O_Z1   + ELT;
constexpr long O_T2   = O_T1   + ELT;
constexpr long SCR    = O_T2   + ELT;
__device__ float g_s[SCR];

__device__ __forceinline__ uint32_t f2tf32(float v){
    uint32_t u;
    asm("cvt.rna.tf32.f32 %0, %1;" : "=r"(u) : "f"(v));
    return u;
}

// ---------------- tf32 tensor-core GEMM: C = A@B (+bias) ----------------
// 64x64x16 CTA tile, 128 threads = 4 warps (2x2), warp tile 32x32 via
// m16n8k8 tf32 MMA. A smem m-major [64][20] (conflict-free frag reads),
// B smem k-major [16][72].
__global__ void k_gemm_tf32(const float* __restrict__ A, int lda, long sA,
                            const float* __restrict__ Bm, int ldb, long sB,
                            float* __restrict__ Cm, int ldc, long sC,
                            int M, int K, int cols, const float* __restrict__ bias)
{
    __shared__ float As[64][20];
    __shared__ float Bs[16][72];
    const float* Ap = A  + (long)blockIdx.z * sA;
    const float* Bp = Bm + (long)blockIdx.z * sB;
    float*       Cp = Cm + (long)blockIdx.z * sC;
    int m0 = blockIdx.y * 64, n0 = blockIdx.x * 64;
    int tid = threadIdx.x;
    int warp = tid >> 5, lane = tid & 31;
    int wm = warp >> 1, wn = warp & 1;
    int qr = lane >> 2, qc = lane & 3;
    float acc[2][4][4] = {};

    for (int k0 = 0; k0 < K; k0 += 16) {
        // A tile: 64 m-rows x 16 k  (coalesced: 16 consecutive k per row)
        #pragma unroll
        for (int i = tid; i < 64*16; i += 128) {
            int r = i >> 4, c = i & 15;
            int gm = m0 + r, gk = k0 + c;
            float v = (gm < M && gk < K) ? Ap[(long)gm * lda + gk] : 0.f;
            As[r][c] = __uint_as_float(f2tf32(v));
        }
        // B tile: 16 k-rows x 64 n (coalesced)
        #pragma unroll
        for (int i = tid; i < 16*64; i += 128) {
            int r = i >> 6, c = i & 63;
            int gk = k0 + r, gn = n0 + c;
            float v = (gk < K && gn < cols) ? Bp[(long)gk * ldb + gn] : 0.f;
            Bs[r][c] = __uint_as_float(f2tf32(v));
        }
        __syncthreads();
        #pragma unroll
        for (int ks = 0; ks < 2; ks++) {
            int kb = ks * 8;
            uint32_t a[2][4], b[4][2];
            #pragma unroll
            for (int mi = 0; mi < 2; mi++) {
                int mb = wm*32 + mi*16;
                a[mi][0] = __float_as_uint(As[mb+qr  ][kb+qc  ]);
                a[mi][1] = __float_as_uint(As[mb+qr+8][kb+qc  ]);
                a[mi][2] = __float_as_uint(As[mb+qr  ][kb+qc+4]);
                a[mi][3] = __float_as_uint(As[mb+qr+8][kb+qc+4]);
            }
            #pragma unroll
            for (int ni = 0; ni < 4; ni++) {
                int nb = wn*32 + ni*8;
                b[ni][0] = __float_as_uint(Bs[kb+qc  ][nb+qr]);
                b[ni][1] = __float_as_uint(Bs[kb+qc+4][nb+qr]);
            }
            #pragma unroll
            for (int mi = 0; mi < 2; mi++)
                #pragma unroll
                for (int ni = 0; ni < 4; ni++) {
                    asm volatile(
                        "mma.sync.aligned.m16n8k8.row.col.f32.tf32.tf32.f32 "
                        "{%0,%1,%2,%3}, {%4,%5,%6,%7}, {%8,%9}, {%0,%1,%2,%3};"
                        : "+f"(acc[mi][ni][0]), "+f"(acc[mi][ni][1]),
                          "+f"(acc[mi][ni][2]), "+f"(acc[mi][ni][3])
                        : "r"(a[mi][0]), "r"(a[mi][1]), "r"(a[mi][2]), "r"(a[mi][3]),
                          "r"(b[ni][0]), "r"(b[ni][1]));
                }
        }
        __syncthreads();
    }
    #pragma unroll
    for (int mi = 0; mi < 2; mi++) {
        #pragma unroll
        for (int ni = 0; ni < 4; ni++) {
            int row = m0 + wm*32 + mi*16 + qr;
            int col = n0 + wn*32 + ni*8 + qc*2;
            float b0 = 0.f, b1 = 0.f;
            if (bias) { b0 = (col < cols) ? bias[col] : 0.f;
                        b1 = (col+1 < cols) ? bias[col+1] : 0.f; }
            if (row < M) {
                if (col   < cols) Cp[(long)row*ldc + col  ] = acc[mi][ni][0] + b0;
                if (col+1 < cols) Cp[(long)row*ldc + col+1] = acc[mi][ni][1] + b1;
            }
            if (row + 8 < M) {
                if (col   < cols) Cp[(long)(row+8)*ldc + col  ] = acc[mi][ni][2] + b0;
                if (col+1 < cols) Cp[(long)(row+8)*ldc + col+1] = acc[mi][ni][3] + b1;
            }
        }
    }
}

// ---------------- fp32 SGEMM (kept for tiny P gemm) ----------------
__global__ void k_gemm(const float* __restrict__ A, int lda, long sA,
                       const float* __restrict__ Bm, int ldb, long sB,
                       float* __restrict__ Cm, int ldc, long sC,
                       int M, int K, int cols, const float* __restrict__ bias)
{
    __shared__ __align__(16) float As[16][64];
    __shared__ __align__(16) float Bs[16][64];
    const float* Ap = A  + (long)blockIdx.z * sA;
    const float* Bp = Bm + (long)blockIdx.z * sB;
    float*       Cp = Cm + (long)blockIdx.z * sC;
    int m0 = blockIdx.y * 64, n0 = blockIdx.x * 64;
    int tid = threadIdx.x;
    int ty = tid >> 4, tx = tid & 15;
    int arow = tid >> 2, akq = (tid & 3) << 2;
    int brow = tid >> 4, bnq = (tid & 15) << 2;
    float acc[4][4] = {};
    for (int k0 = 0; k0 < K; k0 += 16) {
        int am = m0 + arow;
        #pragma unroll
        for (int i = 0; i < 4; i++) {
            int kk = k0 + akq + i;
            As[akq + i][arow] = (am < M && kk < K) ? Ap[(long)am * lda + kk] : 0.f;
        }
        int bk = k0 + brow;
        #pragma unroll
        for (int i = 0; i < 4; i++) {
            int bn = n0 + bnq + i;
            Bs[brow][bnq + i] = (bk < K && bn < cols) ? Bp[(long)bk * ldb + bn] : 0.f;
        }
        __syncthreads();
        #pragma unroll
        for (int k = 0; k < 16; k++) {
            float4 av = *(const float4*)&As[k][ty << 2];
            float4 bv = *(const float4*)&Bs[k][tx << 2];
            float ax[4] = {av.x, av.y, av.z, av.w};
            float bx[4] = {bv.x, bv.y, bv.z, bv.w};
            #pragma unroll
            for (int i = 0; i < 4; i++)
                #pragma unroll
                for (int j = 0; j < 4; j++)
                    acc[i][j] += ax[i] * bx[j];
        }
        __syncthreads();
    }
    #pragma unroll
    for (int i = 0; i < 4; i++) {
        int m = m0 + (ty << 2) + i;
        if (m >= M) continue;
        #pragma unroll
        for (int j = 0; j < 4; j++) {
            int n = n0 + (tx << 2) + j;
            if (n < cols) Cp[(long)m * ldc + n] = acc[i][j] + (bias ? bias[n] : 0.f);
        }
    }
}

// ---------------- small setup kernels ----------------
__global__ void k_A(const float* adj, const float* mask, float* A){
    int i = blockIdx.x * 256 + threadIdx.x;
    if (i < N_*N_) A[i] = adj[i] + mask[i];
}
__global__ void k_rs(const float* A, float* rs){
    int n = blockIdx.x * 32 + threadIdx.x;
    if (n < N_) { float s = 0; for (int j = 0; j < N_; j++) s += A[n*N_+j]; rs[n] = s; }
}
__global__ void k_W(const float* wn, const float* dn, const float* w3, const float* d3,
                    float* Wout){
    __shared__ float bufA[4096];
    __shared__ float bufB[4096];
    __shared__ float dd[64];
    int s = blockIdx.x;
    const float* w = (s == 0) ? wn : w3 + (s-1)*4096;
    const float* d = (s == 0) ? dn : d3 + (s-1)*64;
    int tid = threadIdx.x;
    for (int i = tid; i < 4096; i += 1024) bufA[i] = w[i];
    if (tid < 64) dd[tid] = fminf(fmaxf(d[tid], 0.f), 1.f);
    __syncthreads();
    int row = tid >> 4, j0 = (tid & 15) << 2;
    float a0[4] = {};
    for (int k = 0; k < 64; k++) {
        float wk = bufA[row*64 + k] * dd[k];
        #pragma unroll
        for (int j = 0; j < 4; j++) a0[j] += wk * bufA[(j0+j)*64 + k];
    }
    __syncthreads();
    #pragma unroll
    for (int j = 0; j < 4; j++) bufB[row*64 + j0 + j] = a0[j];
    __syncthreads();
    float a1[4] = {};
    for (int k = 0; k < 64; k++) {
        float m1 = bufB[row*64 + k];
        #pragma unroll
        for (int j = 0; j < 4; j++) a1[j] += m1 * bufB[k*64 + j0 + j];
    }
    __syncthreads();
    #pragma unroll
    for (int j = 0; j < 4; j++) bufA[row*64 + j0 + j] = a1[j];
    __syncthreads();
    float a2[4] = {};
    for (int k = 0; k < 64; k++) {
        float m2 = bufA[row*64 + k];
        #pragma unroll
        for (int j = 0; j < 4; j++) a2[j] += m2 * bufB[k*64 + j0 + j];
    }
    #pragma unroll
    for (int j = 0; j < 4; j++)
        Wout[s*4096 + row*64 + j0 + j] = 1.6f*bufB[row*64 + j0 + j] - 0.6f*a2[j];
}
__global__ void k_em(const float* x, const float* w3, const float* w4,
                     float* em, float* u3, float* u4){
    int bn = blockIdx.x;
    __shared__ float ems[12];
    int t = threadIdx.x;
    if (t < 12) {
        const float* xp = x + ((long)bn*12 + t)*64;
        float s = 0;
        #pragma unroll 8
        for (int c = 0; c < 64; c++) s += xp[c];
        ems[t] = s * (1.f/64.f);
        em[bn*12 + t] = ems[t];
    }
    __syncthreads();
    if (t < 12) {
        float s3 = 0, s4 = 0;
        #pragma unroll
        for (int tt = 0; tt < 12; tt++){ s3 += ems[tt]*w3[tt*12+t]; s4 += ems[tt]*w4[tt*12+t]; }
        u3[bn*12+t] = s3; u4[bn*12+t] = s4;
    }
}
__global__ void k_S(const float* u3, const float* u4, float* S3, float* S4, float* C34){
    int b = blockIdx.x, tid = threadIdx.x;
    int o = tid/12, p = tid%12;
    float c = 0, s3 = 0, s4 = 0;
    for (int n = 0; n < N_; n++){
        float a = u3[(b*N_+n)*12+o], r = u4[(b*N_+n)*12+p];
        c += a*r;
        if (p == 0) s3 += a;
        if (o == 0) s4 += r;
    }
    C34[b*144+tid] = c;
    if (p == 0) S3[b*12+o] = s3;
    if (o == 0) S4[b*12+p] = s4;
}
__global__ void k_attE(const float* u3, const float* u4, const float* S3, const float* S4,
                       const float* C34, const float* P, const float* em,
                       const float* alphaE, float* attE, float* coefE){
    int bn = blockIdx.x; int b = bn / N_; int n = bn % N_;
    int tid = threadIdx.x;
    int o = tid/12, p = tid%12;
    __shared__ float at[144], ems[12];
    float l = (float)N_*u3[bn*12+o]*u4[bn*12+p] + u3[bn*12+o]*S4[b*12+p]
            + S3[b*12+o]*u4[bn*12+p] + C34[b*144+tid];
    float a = sg(l);
    at[tid] = a; attE[(long)bn*144+tid] = a;
    if (tid < 12) ems[tid] = em[bn*12+tid];
    __syncthreads();
    if (tid < 12) {
        float wv = 0;
        #pragma unroll
        for (int oo = 0; oo < 12; oo++) wv += ems[oo]*at[oo*12+tid];
        coefE[bn*12+tid] = 0.5f*sg(alphaE[n])*P[bn*12+tid] + wv;
    }
}
__global__ void k_base(const float* coefE, const float* fw, float* base){
    int b = blockIdx.y, t = blockIdx.x, c = threadIdx.x;
    float s = 0;
    #pragma unroll 4
    for (int n = 0; n < N_; n++) s += fw[n*64+c] * coefE[(b*N_+n)*12+t];
    base[(b*12+t)*64+c] = s;
}
__global__ void k_R(const float* attE, const float* fw, float* R){
    int b = blockIdx.y, tp = blockIdx.x, c = threadIdx.x;
    float s = 0;
    #pragma unroll 4
    for (int n = 0; n < N_; n++) s += attE[((long)b*N_+n)*144+tp] * fw[n*64+c];
    R[((long)b*144+tp)*64+c] = s;
}
__global__ void k_g0(const float* fw, const float* alphaE, const float* rs, float* g0){
    int c = threadIdx.x; float s = 0;
    for (int n = 0; n < N_; n++) s += fw[n*64+c]*sg(alphaE[n])*rs[n];
    g0[c] = 0.5f*s;
}
__global__ void k_al(const float* x, const float* w3, const float* w4,
                     float* al, float* ar){
    __shared__ float w3s[144], w4s[144];
    int bn = blockIdx.x, c = threadIdx.x;
    for (int i = c; i < 144; i += 64){ w3s[i] = w3[i]; w4s[i] = w4[i]; }
    __syncthreads();
    float xr[12];
    const float* xp = x + (long)bn*768 + c;
    #pragma unroll
    for (int t = 0; t < 12; t++) xr[t] = xp[t*64];
    #pragma unroll
    for (int o = 0; o < 12; o++){
        float a = 0, r = 0;
        #pragma unroll
        for (int t = 0; t < 12; t++){ a += xr[t]*w3s[t*12+o]; r += xr[t]*w4s[t*12+o]; }
        al[((long)bn*12+o)*64+c] = a; ar[((long)bn*12+o)*64+c] = r;
    }
}
__global__ void k_attN(const float* al, const float* ar, float* attN){
    int c = blockIdx.x, b = blockIdx.y;
    int tid = threadIdx.x;                 // 144
    int o = tid/12, p = tid%12;
    __shared__ float alc[32*12], arc[32*12];
    float acc = 0;
    for (int n0 = 0; n0 < N_; n0 += 32){
        int cnt = min(32, N_ - n0);
        __syncthreads();
        for (int i = tid; i < cnt*12; i += 144){
            int nn = i/12, oo = i%12;
            long base = (((long)b*N_ + n0 + nn)*12 + oo)*64 + c;
            alc[i] = al[base]; arc[i] = ar[base];
        }
        __syncthreads();
        for (int i = 0; i < cnt; i++) acc += alc[i*12+o]*arc[i*12+p];
    }
    attN[((long)b*64+c)*144 + tid] = sg(acc);
}
__global__ void k_x0n(const float* x, const float* Sn, const float* xw,
                      const float* attN, const float* alphaN, float* x0n){
    int bn = blockIdx.x; int b = bn / N_, n = bn % N_;
    int c = threadIdx.x;
    __shared__ float xs[12][64];
    const float* xp = x + (long)bn*768;
    #pragma unroll
    for (int t = 0; t < 12; t++) xs[t][c] = xp[t*64+c];
    __syncthreads();
    float aN = 0.5f*sg(alphaN[n]);
    const float* an = attN + ((long)b*64+c)*144;
    #pragma unroll
    for (int o = 0; o < 12; o++){
        float tn = 0;
        #pragma unroll
        for (int p = 0; p < 12; p++) tn += an[o*12+p]*xs[p][c];
        long idx = (long)bn*768 + o*64 + c;
        x0n[idx] = aN*Sn[idx] + tn + xw[idx] - xs[o][c];
    }
}
__global__ void k_mhsa(const float* q, const float* k, const float* v,
                       float* z0, float* z){
    int h = blockIdx.x, b = blockIdx.y;
    __shared__ __align__(16) float Ks[N_*DK_];
    __shared__ __align__(16) float Vs[N_*DV_];
    int tid = threadIdx.x;
    for (int i = tid; i < N_*DK_; i += 256){
        int n = i/DK_, d = i%DK_;
        Ks[i] = k[((long)b*N_+n)*TC_ + h*DK_ + d];
    }
    for (int i = tid; i < N_*DV_; i += 256){
        int n = i/DV_, d = i%DV_;
        Vs[i] = v[((long)b*N_+n)*256 + h*DV_ + d];
    }
    __syncthreads();
    const float4* K4 = (const float4*)Ks;
    const float4* V4 = (const float4*)Vs;
    for (int r = 0; r < 2; r++){
        int n = tid + r*256;
        if (n >= N_) break;
        float qr[DK_];
        const float* qp = q + ((long)b*N_+n)*TC_ + h*DK_;
        #pragma unroll
        for (int d = 0; d < DK_; d++) qr[d] = qp[d];
        float mmax = -1e30f, l = 0.f, acc[DV_] = {};
        for (int m = 0; m < N_; m++){
            float s = 0;
            #pragma unroll
            for (int i = 0; i < 6; i++){
                float4 kv = K4[m*6+i];
                s += qr[i*4+0]*kv.x + qr[i*4+1]*kv.y + qr[i*4+2]*kv.z + qr[i*4+3]*kv.w;
            }
            s *= NORM_;
            float nm = fmaxf(mmax, s);
            float e0 = __expf(mmax - nm);
            float e1 = __expf(s - nm);
            l = l*e0 + e1;
            float4 v0 = V4[m*2+0], v1 = V4[m*2+1];
            acc[0] = acc[0]*e0 + e1*v0.x; acc[1] = acc[1]*e0 + e1*v0.y;
            acc[2] = acc[2]*e0 + e1*v0.z; acc[3] = acc[3]*e0 + e1*v0.w;
            acc[4] = acc[4]*e0 + e1*v1.x; acc[5] = acc[5]*e0 + e1*v1.y;
            acc[6] = acc[6]*e0 + e1*v1.z; acc[7] = acc[7]*e0 + e1*v1.w;
            mmax = nm;
        }
        float inv = 1.f/l;
        #pragma unroll
        for (int j = 0; j < DV_; j++){
            int flat = h*DV_ + j;
            int g = flat >> 6, c = flat & 63;
            long idx = (((long)g*B_+b)*N_+n)*64 + c;
            float val = acc[j]*inv;
            z0[idx] = val; z[idx] = val;
        }
    }
}
__global__ void k_att3(const float* z, const float* w31, const float* w41, float* att3){
    int gb = blockIdx.x, c = threadIdx.x;
    float s = 0;
    const float* zp = z + (long)gb*N_*64 + c;
    #pragma unroll 4
    for (int n = 0; n < N_; n++){ float v = zp[n*64]; s += v*v; }
    att3[gb*64+c] = sg(w31[0]*w41[0]*s);
}
__global__ void k_step(const float* zin, const float* Sz, const float* zw,
                       const float* z0, const float* att3, const float* alpha3,
                       float* zout, float* x1s, int step){
    long idx = (long)blockIdx.x*256 + threadIdx.x;
    if (idx >= G4) return;
    int c = idx & 63;
    long r = idx >> 6;
    int n = r % N_; long r2 = r / N_;
    int b = r2 % B_; int g = (int)(r2 / B_);
    float zv = zin[idx];
    float out = 0.5f*sg(alpha3[g*N_+n])*Sz[idx] + att3[(g*B_+b)*64+c]*zv
              + zw[idx] + z0[idx] - 2.f*zv;
    zout[idx] = out;
    x1s[(((long)b*N_+n)*12 + step*4 + g)*64 + c] = out;
}
__global__ void k_clip(const float* x1s, const float* x0n, const float* clip, float* x1c){
    long idx = (long)blockIdx.x*256 + threadIdx.x;
    if (idx >= ELT) return;
    float hi = x0n[idx] + clip[0], lo = x0n[idx] - clip[0];
    float v = x1s[idx];
    if (hi - v < 0.f) v = hi;
    if (lo - v > 0.f) v = lo;
    x1c[idx] = v;
}
__global__ void k_xe(const float* em, const float* base, const float* g0,
                     const float* R, const float* fb, float* xe){
    int bm = blockIdx.x; int b = bm / N_;
    int c = threadIdx.x;
    float emr[12];
    #pragma unroll
    for (int t = 0; t < 12; t++) emr[t] = em[bm*12+t];
    float g0c = g0[c], fbc = fb[c];
    #pragma unroll
    for (int t = 0; t < 12; t++){
        float acc = base[(b*12+t)*64+c] + emr[t]*g0c + fbc;
        #pragma unroll
        for (int tp = 0; tp < 12; tp++)
            acc += emr[tp]*R[((long)b*144 + tp*12 + t)*64 + c];
        xe[((long)bm*12+t)*64+c] = acc;
    }
}
__global__ void k_final1(const float* xg, const float* xl, const float* xe,
                         const float* res, float* z1){
    long idx = (long)blockIdx.x*256 + threadIdx.x;
    if (idx >= ELT) return;
    float a = xg[idx], b = xl[idx], e = xe[idx];
    float sa = sg(a), sb = sg(b), se = sg(e);
    z1[idx] = (a*(sb+se) + b*(se+sa) + e*(sb+sa) + res[idx]) * (1.f/6.f);
}
__global__ void k_final2(const float* t1, const float* t2, float* out){
    long idx = (long)blockIdx.x*256 + threadIdx.x;
    if (idx >= ELT) return;
    out[idx] = fmaxf(sg(t1[idx]) + t2[idx], 0.f);
}

// ---------------- host ----------------
static void gemmT(const float* A, int lda, long sA, const float* B, int ldb, long sB,
                  float* C, int ldc, long sC, int M, int K, int cols,
                  const float* bias, int batch){
    dim3 g((cols+63)/64, (M+63)/64, batch);
    k_gemm_tf32<<<g, 128>>>(A, lda, sA, B, ldb, sB, C, ldc, sC, M, K, cols, bias);
}
static void gemmF(const float* A, int lda, long sA, const float* B, int ldb, long sB,
                  float* C, int ldc, long sC, int M, int K, int cols,
                  const float* bias, int batch){
    dim3 g((cols+63)/64, (M+63)/64, batch);
    k_gemm<<<g, 256>>>(A, lda, sA, B, ldb, sB, C, ldc, sC, M, K, cols, bias);
}

extern "C" void kernel_launch(void* const* d_in, const int* in_sizes, int n_in,
                              void* d_out, int out_size){
    const float* x      = (const float*)d_in[0];
    const float* adj    = (const float*)d_in[1];
    const float* mask   = (const float*)d_in[2];
    const float* w3_12  = (const float*)d_in[3];
    const float* w4_12  = (const float*)d_in[4];
    const float* w3_1   = (const float*)d_in[5];
    const float* w4_1   = (const float*)d_in[6];
    const float* alphaN = (const float*)d_in[7];
    const float* w_n11  = (const float*)d_in[8];
    const float* d_n11  = (const float*)d_in[9];
    const float* alphaE = (const float*)d_in[10];
    const float* alpha3 = (const float*)d_in[11];
    const float* w_3    = (const float*)d_in[12];
    const float* d_3    = (const float*)d_in[13];
    const float* wq     = (const float*)d_in[14];
    const float* bq     = (const float*)d_in[15];
    const float* wk     = (const float*)d_in[16];
    const float* bk     = (const float*)d_in[17];
    const float* wv     = (const float*)d_in[18];
    const float* bv     = (const float*)d_in[19];
    const float* fc1w   = (const float*)d_in[20];
    const float* fc1b   = (const float*)d_in[21];
    const float* fc2w   = (const float*)d_in[22];
    const float* fc2b   = (const float*)d_in[23];
    const float* fcew   = (const float*)d_in[24];
    const float* fceb   = (const float*)d_in[25];
    const float* clip   = (const float*)d_in[26];
    float* out = (float*)d_out;

    float* S;
    cudaGetSymbolAddress((void**)&S, g_s);
    float *A = S+O_A, *RS = S+O_RS, *W = S+O_W, *EM = S+O_EM, *U3 = S+O_U3, *U4 = S+O_U4;
    float *P = S+O_P, *S3 = S+O_S3, *S4 = S+O_S4, *C34 = S+O_C34, *ATTE = S+O_ATTE;
    float *COEFE = S+O_COEFE, *BASE = S+O_BASE, *R = S+O_R, *G0 = S+O_G0, *SN = S+O_SN;
    float *AL = S+O_AL, *AR = S+O_AR, *ATTN = S+O_ATTN, *XW = S+O_XW, *X0N = S+O_X0N;
    float *Q = S+O_Q, *K = S+O_K, *V = S+O_V, *Z0 = S+O_Z0, *Z = S+O_Z;
    float *SZ = S+O_SZ, *ZW = S+O_ZW, *ATT3 = S+O_ATT3, *X1S = S+O_X1S, *X1C = S+O_X1C;
    float *XG = S+O_XG, *XL = S+O_XL, *XE = S+O_XE, *Z1 = S+O_Z1, *T1 = S+O_T1, *T2 = S+O_T2;

    k_A<<<(N_*N_+255)/256, 256>>>(adj, mask, A);
    k_rs<<<(N_+31)/32, 32>>>(A, RS);
    k_W<<<5, 1024>>>(w_n11, d_n11, w_3, d_3, W);
    k_em<<<B_*N_, 32>>>(x, w3_12, w4_12, EM, U3, U4);
    k_S<<<B_, 144>>>(U3, U4, S3, S4, C34);
    gemmF(A, N_, 0, EM, 12, (long)N_*12, P, 12, (long)N_*12, N_, N_, 12, nullptr, B_);
    k_attE<<<B_*N_, 144>>>(U3, U4, S3, S4, C34, P, EM, alphaE, ATTE, COEFE);
    k_base<<<dim3(12, B_), 64>>>(COEFE, fcew, BASE);
    k_R<<<dim3(144, B_), 64>>>(ATTE, fcew, R);
    k_g0<<<1, 64>>>(fcew, alphaE, RS, G0);
    gemmT(A, N_, 0, x, TC_, (long)N_*TC_, SN, TC_, (long)N_*TC_, N_, N_, TC_, nullptr, B_);
    gemmT(x, 64, 0, W, 64, 0, XW, 64, 0, B_*N_*T_, 64, 64, nullptr, 1);
    k_al<<<B_*N_, 64>>>(x, w3_12, w4_12, AL, AR);
    k_attN<<<dim3(64, B_), 144>>>(AL, AR, ATTN);
    k_x0n<<<B_*N_, 64>>>(x, SN, XW, ATTN, alphaN, X0N);
    gemmT(x, TC_, 0, wq, TC_, 0, Q, TC_, 0, B_*N_, TC_, TC_, bq, 1);
    gemmT(x, TC_, 0, wk, TC_, 0, K, TC_, 0, B_*N_, TC_, TC_, bk, 1);
    gemmT(x, TC_, 0, wv, 256, 0, V, 256, 0, B_*N_, TC_, 256, bv, 1);
    k_mhsa<<<dim3(NH_, B_), 256>>>(Q, K, V, Z0, Z);
    for (int step = 0; step < 3; step++){
        gemmT(A, N_, 0, Z, 64, (long)N_*64, SZ, 64, (long)N_*64, N_, N_, 64, nullptr, 64);
        gemmT(Z, 64, 16L*N_*64, W + 4096, 64, 4096, ZW, 64, 16L*N_*64, B_*N_, 64, 64, nullptr, 4);
        k_att3<<<64, 64>>>(Z, w3_1, w4_1, ATT3);
        k_step<<<(int)((G4+255)/256), 256>>>(Z, SZ, ZW, Z0, ATT3, alpha3, Z, X1S, step);
    }
    k_clip<<<(int)((ELT+255)/256), 256>>>(X1S, X0N, clip, X1C);
    gemmT(X1C, 64, 0, fc1w, 64, 0, XG, 64, 0, B_*N_*T_, 64, 64, fc1b, 1);
    gemmT(X0N, 64, 0, fc1w, 64, 0, XL, 64, 0, B_*N_*T_, 64, 64, fc1b, 1);
    k_xe<<<B_*N_, 64>>>(EM, BASE, G0, R, fceb, XE);
    k_final1<<<(int)((ELT+255)/256), 256>>>(XG, XL, XE, x, Z1);
    gemmT(x, 64, 0, fc2w, 64, 0, T1, 64, 0, B_*N_*T_, 64, 64, fc2b, 1);
    gemmT(Z1, 64, 0, fc2w, 64, 0, T2, 64, 0, B_*N_*T_, 64, 64, fc2b, 1);
    k_final2<<<(int)((ELT+255)/256), 256>>>(T1, T2, out);
}

// round 9
// speedup vs baseline: 1.6939x; 1.6939x over previous
#include <cuda_runtime.h>
#include <math.h>
#include <stdint.h>

#define B_  16
#define N_  307
#define T_  12
#define C_  64
#define TC_ 768
#define NH_ 32
#define DK_ 24
#define DV_ 8
#define NORM_ 0.2041241452319315f

__device__ __forceinline__ float sg(float x){ return 1.f/(1.f+__expf(-x)); }

// ---------------- scratch offsets (floats) ----------------
constexpr long ELT = (long)B_*N_*T_*C_;   // 3772416
constexpr long G4  = 4L*B_*N_*C_;         // 1257472
constexpr long O_A    = 0;
constexpr long O_RS   = O_A    + 94272;
constexpr long O_W    = O_RS   + 512;
constexpr long O_EM   = O_W    + 5*4096;
constexpr long O_U3   = O_EM   + 58944;
constexpr long O_U4   = O_U3   + 58944;
constexpr long O_P    = O_U4   + 58944;
constexpr long O_S3   = O_P    + 58944;
constexpr long O_S4   = O_S3   + 256;
constexpr long O_C34  = O_S4   + 256;
constexpr long O_ATTE = O_C34  + 2304;
constexpr long O_COEFE= O_ATTE + (long)B_*N_*144;
constexpr long O_BASE = O_COEFE+ 58944;
constexpr long O_R    = O_BASE + 12288;
constexpr long O_G0   = O_R    + 147456;
constexpr long O_SN   = O_G0   + 64;
constexpr long O_AL   = O_SN   + ELT;
constexpr long O_AR   = O_AL   + ELT;
constexpr long O_ATTN = O_AR   + ELT;
constexpr long O_XW   = O_ATTN + (long)B_*C_*144;
constexpr long O_X0N  = O_XW   + ELT;
constexpr long O_QKV  = O_X0N  + ELT;              // 4912*1792 = 8802304
constexpr long O_Z0   = O_QKV  + 8802304;
constexpr long O_Z    = O_Z0   + G4;
constexpr long O_SZ   = O_Z    + G4;
constexpr long O_ZW   = O_SZ   + G4;
constexpr long O_ATT3 = O_ZW   + G4;
constexpr long O_X1S  = O_ATT3 + 4096;
constexpr long O_X1C  = O_X1S  + ELT;
constexpr long O_XG   = O_X1C  + ELT;
constexpr long O_XL   = O_XG   + ELT;
constexpr long O_XE   = O_XL   + ELT;
constexpr long O_Z1   = O_XE   + ELT;
constexpr long O_T1   = O_Z1   + ELT;
constexpr long O_T2   = O_T1   + ELT;
constexpr long O_WQKV = O_T2   + ELT;              // 768*1792 = 1376256
constexpr long O_BQKV = O_WQKV + 1376256;
constexpr long SCR    = O_BQKV + 2048;
__device__ float g_s[SCR];

// ---------------- high-throughput fp32 SGEMM ----------------
// BM=128, BK=8, 256 threads, double-buffered (register staged, 1 sync/slab).
// BN=128: 8x8 microtile (two 4-wide n-groups); BN=64: 8x4.
template<int BN>
__global__ void __launch_bounds__(256, 2)
k_gemm128(const float* __restrict__ A, int lda, long sA,
          const float* __restrict__ Bm, int ldb, long sB,
          float* __restrict__ Cm, int ldc, long sC,
          int M, int K, int cols, const float* __restrict__ bias)
{
    constexpr int NG = BN/64;
    __shared__ float As[2][8][132];
    __shared__ float Bs[2][8][BN+4];
    const float* Ap = A  + (long)blockIdx.z * sA;
    const float* Bp = Bm + (long)blockIdx.z * sB;
    float*       Cp = Cm + (long)blockIdx.z * sC;
    const int m0 = blockIdx.y * 128, n0 = blockIdx.x * BN;
    const int tid = threadIdx.x;
    const int tx = tid & 15, ty = tid >> 4;
    const int arow = tid >> 1, acol = (tid & 1) << 2;
    const int brow = tid >> 5, bcol = (tid & 31) << 1;
    const int gmA = m0 + arow;
    const long aBase = (long)gmA * lda;
    float aR[4], bR[NG][2];

    auto loadA = [&](int k0){
        #pragma unroll
        for (int i = 0; i < 4; i++) {
            int gk = k0 + acol + i;
            aR[i] = (gmA < M && gk < K) ? Ap[aBase + gk] : 0.f;
        }
    };
    auto loadB = [&](int k0){
        int gk = k0 + brow;
        #pragma unroll
        for (int g = 0; g < NG; g++) {
            if (gk < K) {
                float2 t = *(const float2*)&Bp[(long)gk*ldb + n0 + g*64 + bcol];
                bR[g][0] = t.x; bR[g][1] = t.y;
            } else { bR[g][0] = 0.f; bR[g][1] = 0.f; }
        }
    };
    auto stsAB = [&](int buf){
        #pragma unroll
        for (int i = 0; i < 4; i++) As[buf][acol+i][arow] = aR[i];
        #pragma unroll
        for (int g = 0; g < NG; g++)
            *(float2*)&Bs[buf][brow][g*64 + bcol] = make_float2(bR[g][0], bR[g][1]);
    };

    loadA(0); loadB(0);
    stsAB(0);
    __syncthreads();

    float acc[8][NG*4];
    #pragma unroll
    for (int i = 0; i < 8; i++)
        #pragma unroll
        for (int j = 0; j < NG*4; j++) acc[i][j] = 0.f;

    int buf = 0;
    for (int k0 = 0; k0 < K; k0 += 8) {
        bool nxt = (k0 + 8 < K);
        if (nxt) { loadA(k0+8); loadB(k0+8); }
        #pragma unroll
        for (int k = 0; k < 8; k++) {
            float4 a0 = *(const float4*)&As[buf][k][ty*8];
            float4 a1 = *(const float4*)&As[buf][k][ty*8+4];
            float av[8] = {a0.x,a0.y,a0.z,a0.w,a1.x,a1.y,a1.z,a1.w};
            float bv[NG*4];
            #pragma unroll
            for (int g = 0; g < NG; g++){
                float4 b = *(const float4*)&Bs[buf][k][g*64 + tx*4];
                bv[g*4+0]=b.x; bv[g*4+1]=b.y; bv[g*4+2]=b.z; bv[g*4+3]=b.w;
            }
            #pragma unroll
            for (int i = 0; i < 8; i++)
                #pragma unroll
                for (int j = 0; j < NG*4; j++)
                    acc[i][j] += av[i]*bv[j];
        }
        if (nxt) { stsAB(buf^1); __syncthreads(); buf ^= 1; }
    }
    #pragma unroll
    for (int g = 0; g < NG; g++) {
        int cb = n0 + g*64 + tx*4;
        float4 bb = make_float4(0.f,0.f,0.f,0.f);
        if (bias) bb = *(const float4*)&bias[cb];
        #pragma unroll
        for (int i = 0; i < 8; i++) {
            int row = m0 + ty*8 + i;
            if (row < M) {
                float4 v = make_float4(acc[i][g*4+0]+bb.x, acc[i][g*4+1]+bb.y,
                                       acc[i][g*4+2]+bb.z, acc[i][g*4+3]+bb.w);
                *(float4*)&Cp[(long)row*ldc + cb] = v;
            }
        }
    }
}

// ---------------- fp32 SGEMM (tiny P gemm, cols=12) ----------------
__global__ void k_gemm(const float* __restrict__ A, int lda, long sA,
                       const float* __restrict__ Bm, int ldb, long sB,
                       float* __restrict__ Cm, int ldc, long sC,
                       int M, int K, int cols, const float* __restrict__ bias)
{
    __shared__ __align__(16) float As[16][64];
    __shared__ __align__(16) float Bs[16][64];
    const float* Ap = A  + (long)blockIdx.z * sA;
    const float* Bp = Bm + (long)blockIdx.z * sB;
    float*       Cp = Cm + (long)blockIdx.z * sC;
    int m0 = blockIdx.y * 64, n0 = blockIdx.x * 64;
    int tid = threadIdx.x;
    int ty = tid >> 4, tx = tid & 15;
    int arow = tid >> 2, akq = (tid & 3) << 2;
    int brow = tid >> 4, bnq = (tid & 15) << 2;
    float acc[4][4] = {};
    for (int k0 = 0; k0 < K; k0 += 16) {
        int am = m0 + arow;
        #pragma unroll
        for (int i = 0; i < 4; i++) {
            int kk = k0 + akq + i;
            As[akq + i][arow] = (am < M && kk < K) ? Ap[(long)am * lda + kk] : 0.f;
        }
        int bk = k0 + brow;
        #pragma unroll
        for (int i = 0; i < 4; i++) {
            int bn = n0 + bnq + i;
            Bs[brow][bnq + i] = (bk < K && bn < cols) ? Bp[(long)bk * ldb + bn] : 0.f;
        }
        __syncthreads();
        #pragma unroll
        for (int k = 0; k < 16; k++) {
            float4 av = *(const float4*)&As[k][ty << 2];
            float4 bv = *(const float4*)&Bs[k][tx << 2];
            float ax[4] = {av.x, av.y, av.z, av.w};
            float bx[4] = {bv.x, bv.y, bv.z, bv.w};
            #pragma unroll
            for (int i = 0; i < 4; i++)
                #pragma unroll
                for (int j = 0; j < 4; j++)
                    acc[i][j] += ax[i] * bx[j];
        }
        __syncthreads();
    }
    #pragma unroll
    for (int i = 0; i < 4; i++) {
        int m = m0 + (ty << 2) + i;
        if (m >= M) continue;
        #pragma unroll
        for (int j = 0; j < 4; j++) {
            int n = n0 + (tx << 2) + j;
            if (n < cols) Cp[(long)m * ldc + n] = acc[i][j] + (bias ? bias[n] : 0.f);
        }
    }
}

// ---------------- QKV weight/bias packing ----------------
__global__ void k_pack(const float* wq, const float* wk, const float* wv,
                       const float* bq, const float* bk, const float* bv,
                       float* Wqkv, float* Bqkv){
    int i = blockIdx.x * 256 + threadIdx.x;
    if (i < 768*1792) {
        int r = i / 1792, c = i % 1792;
        float v = (c < 768) ? wq[r*768 + c]
                : (c < 1536) ? wk[r*768 + (c-768)]
                : wv[r*256 + (c-1536)];
        Wqkv[i] = v;
    }
    if (i < 1792) {
        Bqkv[i] = (i < 768) ? bq[i] : (i < 1536) ? bk[i-768] : bv[i-1536];
    }
}

// ---------------- small setup kernels ----------------
__global__ void k_A(const float* adj, const float* mask, float* A){
    int i = blockIdx.x * 256 + threadIdx.x;
    if (i < N_*N_) A[i] = adj[i] + mask[i];
}
__global__ void k_rs(const float* A, float* rs){
    int n = blockIdx.x * 32 + threadIdx.x;
    if (n < N_) { float s = 0; for (int j = 0; j < N_; j++) s += A[n*N_+j]; rs[n] = s; }
}
__global__ void k_W(const float* wn, const float* dn, const float* w3, const float* d3,
                    float* Wout){
    __shared__ float bufA[4096];
    __shared__ float bufB[4096];
    __shared__ float dd[64];
    int s = blockIdx.x;
    const float* w = (s == 0) ? wn : w3 + (s-1)*4096;
    const float* d = (s == 0) ? dn : d3 + (s-1)*64;
    int tid = threadIdx.x;
    for (int i = tid; i < 4096; i += 1024) bufA[i] = w[i];
    if (tid < 64) dd[tid] = fminf(fmaxf(d[tid], 0.f), 1.f);
    __syncthreads();
    int row = tid >> 4, j0 = (tid & 15) << 2;
    float a0[4] = {};
    for (int k = 0; k < 64; k++) {
        float wk = bufA[row*64 + k] * dd[k];
        #pragma unroll
        for (int j = 0; j < 4; j++) a0[j] += wk * bufA[(j0+j)*64 + k];
    }
    __syncthreads();
    #pragma unroll
    for (int j = 0; j < 4; j++) bufB[row*64 + j0 + j] = a0[j];
    __syncthreads();
    float a1[4] = {};
    for (int k = 0; k < 64; k++) {
        float m1 = bufB[row*64 + k];
        #pragma unroll
        for (int j = 0; j < 4; j++) a1[j] += m1 * bufB[k*64 + j0 + j];
    }
    __syncthreads();
    #pragma unroll
    for (int j = 0; j < 4; j++) bufA[row*64 + j0 + j] = a1[j];
    __syncthreads();
    float a2[4] = {};
    for (int k = 0; k < 64; k++) {
        float m2 = bufA[row*64 + k];
        #pragma unroll
        for (int j = 0; j < 4; j++) a2[j] += m2 * bufB[k*64 + j0 + j];
    }
    #pragma unroll
    for (int j = 0; j < 4; j++)
        Wout[s*4096 + row*64 + j0 + j] = 1.6f*bufB[row*64 + j0 + j] - 0.6f*a2[j];
}
__global__ void k_em(const float* x, const float* w3, const float* w4,
                     float* em, float* u3, float* u4){
    int bn = blockIdx.x;
    __shared__ float ems[12];
    int t = threadIdx.x;
    if (t < 12) {
        const float* xp = x + ((long)bn*12 + t)*64;
        float s = 0;
        #pragma unroll 8
        for (int c = 0; c < 64; c++) s += xp[c];
        ems[t] = s * (1.f/64.f);
        em[bn*12 + t] = ems[t];
    }
    __syncthreads();
    if (t < 12) {
        float s3 = 0, s4 = 0;
        #pragma unroll
        for (int tt = 0; tt < 12; tt++){ s3 += ems[tt]*w3[tt*12+t]; s4 += ems[tt]*w4[tt*12+t]; }
        u3[bn*12+t] = s3; u4[bn*12+t] = s4;
    }
}
__global__ void k_S(const float* u3, const float* u4, float* S3, float* S4, float* C34){
    int b = blockIdx.x, tid = threadIdx.x;
    int o = tid/12, p = tid%12;
    float c = 0, s3 = 0, s4 = 0;
    for (int n = 0; n < N_; n++){
        float a = u3[(b*N_+n)*12+o], r = u4[(b*N_+n)*12+p];
        c += a*r;
        if (p == 0) s3 += a;
        if (o == 0) s4 += r;
    }
    C34[b*144+tid] = c;
    if (p == 0) S3[b*12+o] = s3;
    if (o == 0) S4[b*12+p] = s4;
}
__global__ void k_attE(const float* u3, const float* u4, const float* S3, const float* S4,
                       const float* C34, const float* P, const float* em,
                       const float* alphaE, float* attE, float* coefE){
    int bn = blockIdx.x; int b = bn / N_; int n = bn % N_;
    int tid = threadIdx.x;
    int o = tid/12, p = tid%12;
    __shared__ float at[144], ems[12];
    float l = (float)N_*u3[bn*12+o]*u4[bn*12+p] + u3[bn*12+o]*S4[b*12+p]
            + S3[b*12+o]*u4[bn*12+p] + C34[b*144+tid];
    float a = sg(l);
    at[tid] = a; attE[(long)bn*144+tid] = a;
    if (tid < 12) ems[tid] = em[bn*12+tid];
    __syncthreads();
    if (tid < 12) {
        float wv = 0;
        #pragma unroll
        for (int oo = 0; oo < 12; oo++) wv += ems[oo]*at[oo*12+tid];
        coefE[bn*12+tid] = 0.5f*sg(alphaE[n])*P[bn*12+tid] + wv;
    }
}
__global__ void k_base(const float* coefE, const float* fw, float* base){
    int b = blockIdx.y, t = blockIdx.x, c = threadIdx.x;
    float s = 0;
    #pragma unroll 4
    for (int n = 0; n < N_; n++) s += fw[n*64+c] * coefE[(b*N_+n)*12+t];
    base[(b*12+t)*64+c] = s;
}
__global__ void k_R(const float* attE, const float* fw, float* R){
    int b = blockIdx.y, tp = blockIdx.x, c = threadIdx.x;
    float s = 0;
    #pragma unroll 4
    for (int n = 0; n < N_; n++) s += attE[((long)b*N_+n)*144+tp] * fw[n*64+c];
    R[((long)b*144+tp)*64+c] = s;
}
__global__ void k_g0(const float* fw, const float* alphaE, const float* rs, float* g0){
    int c = threadIdx.x; float s = 0;
    for (int n = 0; n < N_; n++) s += fw[n*64+c]*sg(alphaE[n])*rs[n];
    g0[c] = 0.5f*s;
}
__global__ void k_al(const float* x, const float* w3, const float* w4,
                     float* al, float* ar){
    __shared__ float w3s[144], w4s[144];
    int bn = blockIdx.x, c = threadIdx.x;
    for (int i = c; i < 144; i += 64){ w3s[i] = w3[i]; w4s[i] = w4[i]; }
    __syncthreads();
    float xr[12];
    const float* xp = x + (long)bn*768 + c;
    #pragma unroll
    for (int t = 0; t < 12; t++) xr[t] = xp[t*64];
    #pragma unroll
    for (int o = 0; o < 12; o++){
        float a = 0, r = 0;
        #pragma unroll
        for (int t = 0; t < 12; t++){ a += xr[t]*w3s[t*12+o]; r += xr[t]*w4s[t*12+o]; }
        al[((long)bn*12+o)*64+c] = a; ar[((long)bn*12+o)*64+c] = r;
    }
}
__global__ void k_attN(const float* al, const float* ar, float* attN){
    int c = blockIdx.x, b = blockIdx.y;
    int tid = threadIdx.x;                 // 144
    int o = tid/12, p = tid%12;
    __shared__ float alc[32*12], arc[32*12];
    float acc = 0;
    for (int n0 = 0; n0 < N_; n0 += 32){
        int cnt = min(32, N_ - n0);
        __syncthreads();
        for (int i = tid; i < cnt*12; i += 144){
            int nn = i/12, oo = i%12;
            long base = (((long)b*N_ + n0 + nn)*12 + oo)*64 + c;
            alc[i] = al[base]; arc[i] = ar[base];
        }
        __syncthreads();
        for (int i = 0; i < cnt; i++) acc += alc[i*12+o]*arc[i*12+p];
    }
    attN[((long)b*64+c)*144 + tid] = sg(acc);
}
__global__ void k_x0n(const float* x, const float* Sn, const float* xw,
                      const float* attN, const float* alphaN, float* x0n){
    int bn = blockIdx.x; int b = bn / N_, n = bn % N_;
    int c = threadIdx.x;
    __shared__ float xs[12][64];
    const float* xp = x + (long)bn*768;
    #pragma unroll
    for (int t = 0; t < 12; t++) xs[t][c] = xp[t*64+c];
    __syncthreads();
    float aN = 0.5f*sg(alphaN[n]);
    const float* an = attN + ((long)b*64+c)*144;
    #pragma unroll
    for (int o = 0; o < 12; o++){
        float tn = 0;
        #pragma unroll
        for (int p = 0; p < 12; p++) tn += an[o*12+p]*xs[p][c];
        long idx = (long)bn*768 + o*64 + c;
        x0n[idx] = aN*Sn[idx] + tn + xw[idx] - xs[o][c];
    }
}
// MHSA reading fused QKV layout: row stride 1792; q at +0, k at +768, v at +1536
__global__ void k_mhsa(const float* qkv, float* z0, float* z){
    int h = blockIdx.x, b = blockIdx.y;
    __shared__ __align__(16) float Ks[N_*DK_];
    __shared__ __align__(16) float Vs[N_*DV_];
    int tid = threadIdx.x;
    for (int i = tid; i < N_*DK_; i += 256){
        int n = i/DK_, d = i%DK_;
        Ks[i] = qkv[((long)b*N_+n)*1792 + 768 + h*DK_ + d];
    }
    for (int i = tid; i < N_*DV_; i += 256){
        int n = i/DV_, d = i%DV_;
        Vs[i] = qkv[((long)b*N_+n)*1792 + 1536 + h*DV_ + d];
    }
    __syncthreads();
    const float4* K4 = (const float4*)Ks;
    const float4* V4 = (const float4*)Vs;
    for (int r = 0; r < 2; r++){
        int n = tid + r*256;
        if (n >= N_) break;
        float qr[DK_];
        const float* qp = qkv + ((long)b*N_+n)*1792 + h*DK_;
        #pragma unroll
        for (int d = 0; d < DK_; d++) qr[d] = qp[d];
        float mmax = -1e30f, l = 0.f, acc[DV_] = {};
        for (int m = 0; m < N_; m++){
            float s = 0;
            #pragma unroll
            for (int i = 0; i < 6; i++){
                float4 kv = K4[m*6+i];
                s += qr[i*4+0]*kv.x + qr[i*4+1]*kv.y + qr[i*4+2]*kv.z + qr[i*4+3]*kv.w;
            }
            s *= NORM_;
            float nm = fmaxf(mmax, s);
            float e0 = __expf(mmax - nm);
            float e1 = __expf(s - nm);
            l = l*e0 + e1;
            float4 v0 = V4[m*2+0], v1 = V4[m*2+1];
            acc[0] = acc[0]*e0 + e1*v0.x; acc[1] = acc[1]*e0 + e1*v0.y;
            acc[2] = acc[2]*e0 + e1*v0.z; acc[3] = acc[3]*e0 + e1*v0.w;
            acc[4] = acc[4]*e0 + e1*v1.x; acc[5] = acc[5]*e0 + e1*v1.y;
            acc[6] = acc[6]*e0 + e1*v1.z; acc[7] = acc[7]*e0 + e1*v1.w;
            mmax = nm;
        }
        float inv = 1.f/l;
        #pragma unroll
        for (int j = 0; j < DV_; j++){
            int flat = h*DV_ + j;
            int g = flat >> 6, c = flat & 63;
            long idx = (((long)g*B_+b)*N_+n)*64 + c;
            float val = acc[j]*inv;
            z0[idx] = val; z[idx] = val;
        }
    }
}
__global__ void k_att3(const float* z, const float* w31, const float* w41, float* att3){
    int gb = blockIdx.x, c = threadIdx.x;
    float s = 0;
    const float* zp = z + (long)gb*N_*64 + c;
    #pragma unroll 4
    for (int n = 0; n < N_; n++){ float v = zp[n*64]; s += v*v; }
    att3[gb*64+c] = sg(w31[0]*w41[0]*s);
}
__global__ void k_step(const float* zin, const float* Sz, const float* zw,
                       const float* z0, const float* att3, const float* alpha3,
                       float* zout, float* x1s, int step){
    long idx = (long)blockIdx.x*256 + threadIdx.x;
    if (idx >= G4) return;
    int c = idx & 63;
    long r = idx >> 6;
    int n = r % N_; long r2 = r / N_;
    int b = r2 % B_; int g = (int)(r2 / B_);
    float zv = zin[idx];
    float out = 0.5f*sg(alpha3[g*N_+n])*Sz[idx] + att3[(g*B_+b)*64+c]*zv
              + zw[idx] + z0[idx] - 2.f*zv;
    zout[idx] = out;
    x1s[(((long)b*N_+n)*12 + step*4 + g)*64 + c] = out;
}
__global__ void k_clip(const float* x1s, const float* x0n, const float* clip, float* x1c){
    long idx = (long)blockIdx.x*256 + threadIdx.x;
    if (idx >= ELT) return;
    float hi = x0n[idx] + clip[0], lo = x0n[idx] - clip[0];
    float v = x1s[idx];
    if (hi - v < 0.f) v = hi;
    if (lo - v > 0.f) v = lo;
    x1c[idx] = v;
}
__global__ void k_xe(const float* em, const float* base, const float* g0,
                     const float* R, const float* fb, float* xe){
    int bm = blockIdx.x; int b = bm / N_;
    int c = threadIdx.x;
    float emr[12];
    #pragma unroll
    for (int t = 0; t < 12; t++) emr[t] = em[bm*12+t];
    float g0c = g0[c], fbc = fb[c];
    #pragma unroll
    for (int t = 0; t < 12; t++){
        float acc = base[(b*12+t)*64+c] + emr[t]*g0c + fbc;
        #pragma unroll
        for (int tp = 0; tp < 12; tp++)
            acc += emr[tp]*R[((long)b*144 + tp*12 + t)*64 + c];
        xe[((long)bm*12+t)*64+c] = acc;
    }
}
__global__ void k_final1(const float* xg, const float* xl, const float* xe,
                         const float* res, float* z1){
    long idx = (long)blockIdx.x*256 + threadIdx.x;
    if (idx >= ELT) return;
    float a = xg[idx], b = xl[idx], e = xe[idx];
    float sa = sg(a), sb = sg(b), se = sg(e);
    z1[idx] = (a*(sb+se) + b*(se+sa) + e*(sb+sa) + res[idx]) * (1.f/6.f);
}
__global__ void k_final2(const float* t1, const float* t2, float* out){
    long idx = (long)blockIdx.x*256 + threadIdx.x;
    if (idx >= ELT) return;
    out[idx] = fmaxf(sg(t1[idx]) + t2[idx], 0.f);
}

// ---------------- host ----------------
static void g128(const float* A, int lda, long sA, const float* B, int ldb, long sB,
                 float* C, int ldc, long sC, int M, int K, int cols,
                 const float* bias, int batch){
    if (cols % 128 == 0) {
        dim3 g(cols/128, (M+127)/128, batch);
        k_gemm128<128><<<g, 256>>>(A, lda, sA, B, ldb, sB, C, ldc, sC, M, K, cols, bias);
    } else {
        dim3 g(cols/64, (M+127)/128, batch);
        k_gemm128<64><<<g, 256>>>(A, lda, sA, B, ldb, sB, C, ldc, sC, M, K, cols, bias);
    }
}
static void gemmF(const float* A, int lda, long sA, const float* B, int ldb, long sB,
                  float* C, int ldc, long sC, int M, int K, int cols,
                  const float* bias, int batch){
    dim3 g((cols+63)/64, (M+63)/64, batch);
    k_gemm<<<g, 256>>>(A, lda, sA, B, ldb, sB, C, ldc, sC, M, K, cols, bias);
}

extern "C" void kernel_launch(void* const* d_in, const int* in_sizes, int n_in,
                              void* d_out, int out_size){
    const float* x      = (const float*)d_in[0];
    const float* adj    = (const float*)d_in[1];
    const float* mask   = (const float*)d_in[2];
    const float* w3_12  = (const float*)d_in[3];
    const float* w4_12  = (const float*)d_in[4];
    const float* w3_1   = (const float*)d_in[5];
    const float* w4_1   = (const float*)d_in[6];
    const float* alphaN = (const float*)d_in[7];
    const float* w_n11  = (const float*)d_in[8];
    const float* d_n11  = (const float*)d_in[9];
    const float* alphaE = (const float*)d_in[10];
    const float* alpha3 = (const float*)d_in[11];
    const float* w_3    = (const float*)d_in[12];
    const float* d_3    = (const float*)d_in[13];
    const float* wq     = (const float*)d_in[14];
    const float* bq     = (const float*)d_in[15];
    const float* wk     = (const float*)d_in[16];
    const float* bk     = (const float*)d_in[17];
    const float* wv     = (const float*)d_in[18];
    const float* bv     = (const float*)d_in[19];
    const float* fc1w   = (const float*)d_in[20];
    const float* fc1b   = (const float*)d_in[21];
    const float* fc2w   = (const float*)d_in[22];
    const float* fc2b   = (const float*)d_in[23];
    const float* fcew   = (const float*)d_in[24];
    const float* fceb   = (const float*)d_in[25];
    const float* clip   = (const float*)d_in[26];
    float* out = (float*)d_out;

    float* S;
    cudaGetSymbolAddress((void**)&S, g_s);
    float *A = S+O_A, *RS = S+O_RS, *W = S+O_W, *EM = S+O_EM, *U3 = S+O_U3, *U4 = S+O_U4;
    float *P = S+O_P, *S3 = S+O_S3, *S4 = S+O_S4, *C34 = S+O_C34, *ATTE = S+O_ATTE;
    float *COEFE = S+O_COEFE, *BASE = S+O_BASE, *R = S+O_R, *G0 = S+O_G0, *SN = S+O_SN;
    float *AL = S+O_AL, *AR = S+O_AR, *ATTN = S+O_ATTN, *XW = S+O_XW, *X0N = S+O_X0N;
    float *QKV = S+O_QKV, *Z0 = S+O_Z0, *Z = S+O_Z;
    float *SZ = S+O_SZ, *ZW = S+O_ZW, *ATT3 = S+O_ATT3, *X1S = S+O_X1S, *X1C = S+O_X1C;
    float *XG = S+O_XG, *XL = S+O_XL, *XE = S+O_XE, *Z1 = S+O_Z1, *T1 = S+O_T1, *T2 = S+O_T2;
    float *WQKV = S+O_WQKV, *BQKV = S+O_BQKV;

    k_A<<<(N_*N_+255)/256, 256>>>(adj, mask, A);
    k_rs<<<(N_+31)/32, 32>>>(A, RS);
    k_W<<<5, 1024>>>(w_n11, d_n11, w_3, d_3, W);
    k_pack<<<(768*1792+255)/256, 256>>>(wq, wk, wv, bq, bk, bv, WQKV, BQKV);
    k_em<<<B_*N_, 32>>>(x, w3_12, w4_12, EM, U3, U4);
    k_S<<<B_, 144>>>(U3, U4, S3, S4, C34);
    gemmF(A, N_, 0, EM, 12, (long)N_*12, P, 12, (long)N_*12, N_, N_, 12, nullptr, B_);
    k_attE<<<B_*N_, 144>>>(U3, U4, S3, S4, C34, P, EM, alphaE, ATTE, COEFE);
    k_base<<<dim3(12, B_), 64>>>(COEFE, fcew, BASE);
    k_R<<<dim3(144, B_), 64>>>(ATTE, fcew, R);
    k_g0<<<1, 64>>>(fcew, alphaE, RS, G0);
    g128(A, N_, 0, x, TC_, (long)N_*TC_, SN, TC_, (long)N_*TC_, N_, N_, TC_, nullptr, B_);
    g128(x, 64, 0, W, 64, 0, XW, 64, 0, B_*N_*T_, 64, 64, nullptr, 1);
    k_al<<<B_*N_, 64>>>(x, w3_12, w4_12, AL, AR);
    k_attN<<<dim3(64, B_), 144>>>(AL, AR, ATTN);
    k_x0n<<<B_*N_, 64>>>(x, SN, XW, ATTN, alphaN, X0N);
    g128(x, TC_, 0, WQKV, 1792, 0, QKV, 1792, 0, B_*N_, TC_, 1792, BQKV, 1);
    k_mhsa<<<dim3(NH_, B_), 256>>>(QKV, Z0, Z);
    for (int step = 0; step < 3; step++){
        g128(A, N_, 0, Z, 64, (long)N_*64, SZ, 64, (long)N_*64, N_, N_, 64, nullptr, 64);
        g128(Z, 64, 16L*N_*64, W + 4096, 64, 4096, ZW, 64, 16L*N_*64, B_*N_, 64, 64, nullptr, 4);
        k_att3<<<64, 64>>>(Z, w3_1, w4_1, ATT3);
        k_step<<<(int)((G4+255)/256), 256>>>(Z, SZ, ZW, Z0, ATT3, alpha3, Z, X1S, step);
    }
    k_clip<<<(int)((ELT+255)/256), 256>>>(X1S, X0N, clip, X1C);
    g128(X1C, 64, 0, fc1w, 64, 0, XG, 64, 0, B_*N_*T_, 64, 64, fc1b, 1);
    g128(X0N, 64, 0, fc1w, 64, 0, XL, 64, 0, B_*N_*T_, 64, 64, fc1b, 1);
    k_xe<<<B_*N_, 64>>>(EM, BASE, G0, R, fceb, XE);
    k_final1<<<(int)((ELT+255)/256), 256>>>(XG, XL, XE, x, Z1);
    g128(x, 64, 0, fc2w, 64, 0, T1, 64, 0, B_*N_*T_, 64, 64, fc2b, 1);
    g128(Z1, 64, 0, fc2w, 64, 0, T2, 64, 0, B_*N_*T_, 64, 64, fc2b, 1);
    k_final2<<<(int)((ELT+255)/256), 256>>>(T1, T2, out);
}

// round 11
// speedup vs baseline: 1.9457x; 1.1487x over previous
#include <cuda_runtime.h>
#include <math.h>
#include <stdint.h>

#define B_  16
#define N_  307
#define T_  12
#define C_  64
#define TC_ 768
#define NH_ 32
#define DK_ 24
#define DV_ 8
#define NORM_ 0.2041241452319315f

__device__ __forceinline__ float sg(float x){ return 1.f/(1.f+__expf(-x)); }

// ---------------- scratch offsets (floats) ----------------
constexpr long ELT = (long)B_*N_*T_*C_;
constexpr long G4  = 4L*B_*N_*C_;
constexpr long O_A    = 0;
constexpr long O_RS   = O_A    + 94272;
constexpr long O_W    = O_RS   + 512;
constexpr long O_EM   = O_W    + 5*4096;
constexpr long O_U3   = O_EM   + 58944;
constexpr long O_U4   = O_U3   + 58944;
constexpr long O_P    = O_U4   + 58944;
constexpr long O_S3   = O_P    + 58944;
constexpr long O_S4   = O_S3   + 256;
constexpr long O_C34  = O_S4   + 256;
constexpr long O_ATTE = O_C34  + 2304;
constexpr long O_COEFE= O_ATTE + (long)B_*N_*144;
constexpr long O_BASE = O_COEFE+ 58944;
constexpr long O_R    = O_BASE + 12288;
constexpr long O_G0   = O_R    + 147456;
constexpr long O_SN   = O_G0   + 64;
constexpr long O_AL   = O_SN   + ELT;
constexpr long O_AR   = O_AL   + ELT;
constexpr long O_ATTN = O_AR   + ELT;
constexpr long O_XW   = O_ATTN + (long)B_*C_*144;
constexpr long O_X0N  = O_XW   + ELT;
constexpr long O_QKV  = O_X0N  + ELT;              // 4912*1792
constexpr long O_Z0   = O_QKV  + 8802304;
constexpr long O_Z    = O_Z0   + G4;
constexpr long O_SZ   = O_Z    + G4;
constexpr long O_ZW   = O_SZ   + G4;
constexpr long O_ATT3 = O_ZW   + G4;
constexpr long O_X1S  = O_ATT3 + 4096;
constexpr long O_X1C  = O_X1S  + ELT;
constexpr long O_XG   = O_X1C  + ELT;
constexpr long O_XL   = O_XG   + ELT;
constexpr long O_XE   = O_XL   + ELT;
constexpr long O_Z1   = O_XE   + ELT;
constexpr long O_T1   = O_Z1   + ELT;
constexpr long O_T2   = O_T1   + ELT;
constexpr long SCR    = O_T2   + ELT;
__device__ float g_s[SCR];

__device__ __forceinline__ uint32_t f2tf32(float v){
    uint32_t u;
    asm("cvt.rna.tf32.f32 %0, %1;" : "=r"(u) : "f"(v));
    return u;
}

// ---------------- tf32 mma.sync QKV GEMM ----------------
// C[4912,1792] = x[4912,768] @ [wq|wk|wv] + [bq|bk|bv]
// BM=128, BN=64, BK=16, 256 threads (8 warps 4m x 2n), warp tile 32x32.
// A smem k-major [16][136] (conflict-free frag reads), B [16][72].
// Register-staged double buffering, one sync per slab.
__global__ void __launch_bounds__(256, 2)
k_qkv_mma(const float* __restrict__ x,
          const float* __restrict__ wq, const float* __restrict__ wk,
          const float* __restrict__ wv,
          const float* __restrict__ bq, const float* __restrict__ bk,
          const float* __restrict__ bv,
          float* __restrict__ Cp)
{
    __shared__ float As[2][16][136];
    __shared__ float Bs[2][16][72];
    const int nt = blockIdx.x, mt = blockIdx.y;
    const float* Bsrc; const float* bias; int ldb; int ncol0;
    if (nt < 12)      { Bsrc = wq; bias = bq; ldb = 768; ncol0 = nt*64; }
    else if (nt < 24) { Bsrc = wk; bias = bk; ldb = 768; ncol0 = (nt-12)*64; }
    else              { Bsrc = wv; bias = bv; ldb = 256; ncol0 = (nt-24)*64; }
    const int tid = threadIdx.x;
    const int warp = tid >> 5, lane = tid & 31;
    const int wm = warp >> 1, wn = warp & 1;
    const int qr = lane >> 2, qc = lane & 3;
    const int arow = tid >> 1, acol = (tid & 1) * 8;
    const int brow = tid >> 4, bcol = (tid & 15) * 4;
    const int gm = mt*128 + arow;
    float aR[8]; float4 bR;

    auto loadA = [&](int k0){
        if (gm < 4912) {
            const float4* p = (const float4*)(x + (long)gm*768 + k0 + acol);
            float4 t0 = p[0], t1 = p[1];
            aR[0]=t0.x; aR[1]=t0.y; aR[2]=t0.z; aR[3]=t0.w;
            aR[4]=t1.x; aR[5]=t1.y; aR[6]=t1.z; aR[7]=t1.w;
        } else {
            #pragma unroll
            for (int i = 0; i < 8; i++) aR[i] = 0.f;
        }
    };
    auto loadB = [&](int k0){
        bR = *(const float4*)(Bsrc + (long)(k0 + brow)*ldb + ncol0 + bcol);
    };
    auto sts = [&](int buf){
        #pragma unroll
        for (int i = 0; i < 8; i++)
            As[buf][acol+i][arow] = __uint_as_float(f2tf32(aR[i]));
        float4 c;
        c.x = __uint_as_float(f2tf32(bR.x)); c.y = __uint_as_float(f2tf32(bR.y));
        c.z = __uint_as_float(f2tf32(bR.z)); c.w = __uint_as_float(f2tf32(bR.w));
        *(float4*)&Bs[buf][brow][bcol] = c;
    };

    loadA(0); loadB(0);
    sts(0);
    __syncthreads();

    float acc[2][4][4];
    #pragma unroll
    for (int mi = 0; mi < 2; mi++)
        #pragma unroll
        for (int ni = 0; ni < 4; ni++)
            #pragma unroll
            for (int j = 0; j < 4; j++) acc[mi][ni][j] = 0.f;

    int buf = 0;
    for (int k0 = 0; k0 < 768; k0 += 16) {
        bool nxt = (k0 + 16 < 768);
        if (nxt) { loadA(k0+16); loadB(k0+16); }
        #pragma unroll
        for (int ks = 0; ks < 2; ks++) {
            int kb = ks * 8;
            uint32_t a[2][4], b[4][2];
            #pragma unroll
            for (int mi = 0; mi < 2; mi++) {
                int mrow = wm*32 + mi*16;
                a[mi][0] = __float_as_uint(As[buf][kb+qc  ][mrow+qr  ]);
                a[mi][1] = __float_as_uint(As[buf][kb+qc  ][mrow+qr+8]);
                a[mi][2] = __float_as_uint(As[buf][kb+qc+4][mrow+qr  ]);
                a[mi][3] = __float_as_uint(As[buf][kb+qc+4][mrow+qr+8]);
            }
            #pragma unroll
            for (int ni = 0; ni < 4; ni++) {
                int ncol = wn*32 + ni*8;
                b[ni][0] = __float_as_uint(Bs[buf][kb+qc  ][ncol+qr]);
                b[ni][1] = __float_as_uint(Bs[buf][kb+qc+4][ncol+qr]);
            }
            #pragma unroll
            for (int mi = 0; mi < 2; mi++)
                #pragma unroll
                for (int ni = 0; ni < 4; ni++) {
                    asm volatile(
                        "mma.sync.aligned.m16n8k8.row.col.f32.tf32.tf32.f32 "
                        "{%0,%1,%2,%3}, {%4,%5,%6,%7}, {%8,%9}, {%0,%1,%2,%3};"
                        : "+f"(acc[mi][ni][0]), "+f"(acc[mi][ni][1]),
                          "+f"(acc[mi][ni][2]), "+f"(acc[mi][ni][3])
                        : "r"(a[mi][0]), "r"(a[mi][1]), "r"(a[mi][2]), "r"(a[mi][3]),
                          "r"(b[ni][0]), "r"(b[ni][1]));
                }
        }
        if (nxt) { sts(buf^1); __syncthreads(); buf ^= 1; }
    }

    #pragma unroll
    for (int mi = 0; mi < 2; mi++) {
        #pragma unroll
        for (int ni = 0; ni < 4; ni++) {
            int row = mt*128 + wm*32 + mi*16 + qr;
            int lcol = wn*32 + ni*8 + qc*2;          // within this 64-wide tile's source
            float b0 = bias[ncol0 + lcol], b1 = bias[ncol0 + lcol + 1];
            long gcol = (long)nt*64 + lcol;
            if (row < 4912)
                *(float2*)&Cp[(long)row*1792 + gcol] =
                    make_float2(acc[mi][ni][0] + b0, acc[mi][ni][1] + b1);
            if (row + 8 < 4912)
                *(float2*)&Cp[(long)(row+8)*1792 + gcol] =
                    make_float2(acc[mi][ni][2] + b0, acc[mi][ni][3] + b1);
        }
    }
}

// ---------------- high-throughput fp32 SGEMM ----------------
template<int BN>
__global__ void __launch_bounds__(256, 2)
k_gemm128(const float* __restrict__ A, int lda, long sA,
          const float* __restrict__ Bm, int ldb, long sB,
          float* __restrict__ Cm, int ldc, long sC,
          int M, int K, int cols, const float* __restrict__ bias)
{
    constexpr int NG = BN/64;
    __shared__ float As[2][8][132];
    __shared__ float Bs[2][8][BN+4];
    const float* Ap = A  + (long)blockIdx.z * sA;
    const float* Bp = Bm + (long)blockIdx.z * sB;
    float*       Cp = Cm + (long)blockIdx.z * sC;
    const int m0 = blockIdx.y * 128, n0 = blockIdx.x * BN;
    const int tid = threadIdx.x;
    const int tx = tid & 15, ty = tid >> 4;
    const int arow = tid >> 1, acol = (tid & 1) << 2;
    const int brow = tid >> 5, bcol = (tid & 31) << 1;
    const int gmA = m0 + arow;
    const long aBase = (long)gmA * lda;
    float aR[4], bR[NG][2];
    auto loadA = [&](int k0){
        #pragma unroll
        for (int i = 0; i < 4; i++) {
            int gk = k0 + acol + i;
            aR[i] = (gmA < M && gk < K) ? Ap[aBase + gk] : 0.f;
        }
    };
    auto loadB = [&](int k0){
        int gk = k0 + brow;
        #pragma unroll
        for (int g = 0; g < NG; g++) {
            if (gk < K) {
                float2 t = *(const float2*)&Bp[(long)gk*ldb + n0 + g*64 + bcol];
                bR[g][0] = t.x; bR[g][1] = t.y;
            } else { bR[g][0] = 0.f; bR[g][1] = 0.f; }
        }
    };
    auto stsAB = [&](int buf){
        #pragma unroll
        for (int i = 0; i < 4; i++) As[buf][acol+i][arow] = aR[i];
        #pragma unroll
        for (int g = 0; g < NG; g++)
            *(float2*)&Bs[buf][brow][g*64 + bcol] = make_float2(bR[g][0], bR[g][1]);
    };
    loadA(0); loadB(0);
    stsAB(0);
    __syncthreads();
    float acc[8][NG*4];
    #pragma unroll
    for (int i = 0; i < 8; i++)
        #pragma unroll
        for (int j = 0; j < NG*4; j++) acc[i][j] = 0.f;
    int buf = 0;
    for (int k0 = 0; k0 < K; k0 += 8) {
        bool nxt = (k0 + 8 < K);
        if (nxt) { loadA(k0+8); loadB(k0+8); }
        #pragma unroll
        for (int k = 0; k < 8; k++) {
            float4 a0 = *(const float4*)&As[buf][k][ty*8];
            float4 a1 = *(const float4*)&As[buf][k][ty*8+4];
            float av[8] = {a0.x,a0.y,a0.z,a0.w,a1.x,a1.y,a1.z,a1.w};
            float bv[NG*4];
            #pragma unroll
            for (int g = 0; g < NG; g++){
                float4 b = *(const float4*)&Bs[buf][k][g*64 + tx*4];
                bv[g*4+0]=b.x; bv[g*4+1]=b.y; bv[g*4+2]=b.z; bv[g*4+3]=b.w;
            }
            #pragma unroll
            for (int i = 0; i < 8; i++)
                #pragma unroll
                for (int j = 0; j < NG*4; j++)
                    acc[i][j] += av[i]*bv[j];
        }
        if (nxt) { stsAB(buf^1); __syncthreads(); buf ^= 1; }
    }
    #pragma unroll
    for (int g = 0; g < NG; g++) {
        int cb = n0 + g*64 + tx*4;
        float4 bb = make_float4(0.f,0.f,0.f,0.f);
        if (bias) bb = *(const float4*)&bias[cb];
        #pragma unroll
        for (int i = 0; i < 8; i++) {
            int row = m0 + ty*8 + i;
            if (row < M) {
                float4 v = make_float4(acc[i][g*4+0]+bb.x, acc[i][g*4+1]+bb.y,
                                       acc[i][g*4+2]+bb.z, acc[i][g*4+3]+bb.w);
                *(float4*)&Cp[(long)row*ldc + cb] = v;
            }
        }
    }
}

// ---------------- fp32 SGEMM (tiny P gemm) ----------------
__global__ void k_gemm(const float* __restrict__ A, int lda, long sA,
                       const float* __restrict__ Bm, int ldb, long sB,
                       float* __restrict__ Cm, int ldc, long sC,
                       int M, int K, int cols, const float* __restrict__ bias)
{
    __shared__ __align__(16) float As[16][64];
    __shared__ __align__(16) float Bs[16][64];
    const float* Ap = A  + (long)blockIdx.z * sA;
    const float* Bp = Bm + (long)blockIdx.z * sB;
    float*       Cp = Cm + (long)blockIdx.z * sC;
    int m0 = blockIdx.y * 64, n0 = blockIdx.x * 64;
    int tid = threadIdx.x;
    int ty = tid >> 4, tx = tid & 15;
    int arow = tid >> 2, akq = (tid & 3) << 2;
    int brow = tid >> 4, bnq = (tid & 15) << 2;
    float acc[4][4] = {};
    for (int k0 = 0; k0 < K; k0 += 16) {
        int am = m0 + arow;
        #pragma unroll
        for (int i = 0; i < 4; i++) {
            int kk = k0 + akq + i;
            As[akq + i][arow] = (am < M && kk < K) ? Ap[(long)am * lda + kk] : 0.f;
        }
        int bk = k0 + brow;
        #pragma unroll
        for (int i = 0; i < 4; i++) {
            int bn = n0 + bnq + i;
            Bs[brow][bnq + i] = (bk < K && bn < cols) ? Bp[(long)bk * ldb + bn] : 0.f;
        }
        __syncthreads();
        #pragma unroll
        for (int k = 0; k < 16; k++) {
            float4 av = *(const float4*)&As[k][ty << 2];
            float4 bv = *(const float4*)&Bs[k][tx << 2];
            float ax[4] = {av.x, av.y, av.z, av.w};
            float bx[4] = {bv.x, bv.y, bv.z, bv.w};
            #pragma unroll
            for (int i = 0; i < 4; i++)
                #pragma unroll
                for (int j = 0; j < 4; j++)
                    acc[i][j] += ax[i] * bx[j];
        }
        __syncthreads();
    }
    #pragma unroll
    for (int i = 0; i < 4; i++) {
        int m = m0 + (ty << 2) + i;
        if (m >= M) continue;
        #pragma unroll
        for (int j = 0; j < 4; j++) {
            int n = n0 + (tx << 2) + j;
            if (n < cols) Cp[(long)m * ldc + n] = acc[i][j] + (bias ? bias[n] : 0.f);
        }
    }
}

// ---------------- small setup kernels ----------------
__global__ void k_A(const float* adj, const float* mask, float* A){
    int i = blockIdx.x * 256 + threadIdx.x;
    if (i < N_*N_) A[i] = adj[i] + mask[i];
}
__global__ void k_rs(const float* A, float* rs){
    int n = blockIdx.x * 32 + threadIdx.x;
    if (n < N_) { float s = 0; for (int j = 0; j < N_; j++) s += A[n*N_+j]; rs[n] = s; }
}
__global__ void k_W(const float* wn, const float* dn, const float* w3, const float* d3,
                    float* Wout){
    __shared__ float bufA[4096];
    __shared__ float bufB[4096];
    __shared__ float dd[64];
    int s = blockIdx.x;
    const float* w = (s == 0) ? wn : w3 + (s-1)*4096;
    const float* d = (s == 0) ? dn : d3 + (s-1)*64;
    int tid = threadIdx.x;
    for (int i = tid; i < 4096; i += 1024) bufA[i] = w[i];
    if (tid < 64) dd[tid] = fminf(fmaxf(d[tid], 0.f), 1.f);
    __syncthreads();
    int row = tid >> 4, j0 = (tid & 15) << 2;
    float a0[4] = {};
    for (int k = 0; k < 64; k++) {
        float wk = bufA[row*64 + k] * dd[k];
        #pragma unroll
        for (int j = 0; j < 4; j++) a0[j] += wk * bufA[(j0+j)*64 + k];
    }
    __syncthreads();
    #pragma unroll
    for (int j = 0; j < 4; j++) bufB[row*64 + j0 + j] = a0[j];
    __syncthreads();
    float a1[4] = {};
    for (int k = 0; k < 64; k++) {
        float m1 = bufB[row*64 + k];
        #pragma unroll
        for (int j = 0; j < 4; j++) a1[j] += m1 * bufB[k*64 + j0 + j];
    }
    __syncthreads();
    #pragma unroll
    for (int j = 0; j < 4; j++) bufA[row*64 + j0 + j] = a1[j];
    __syncthreads();
    float a2[4] = {};
    for (int k = 0; k < 64; k++) {
        float m2 = bufA[row*64 + k];
        #pragma unroll
        for (int j = 0; j < 4; j++) a2[j] += m2 * bufB[k*64 + j0 + j];
    }
    #pragma unroll
    for (int j = 0; j < 4; j++)
        Wout[s*4096 + row*64 + j0 + j] = 1.6f*bufB[row*64 + j0 + j] - 0.6f*a2[j];
}
__global__ void k_em(const float* x, const float* w3, const float* w4,
                     float* em, float* u3, float* u4){
    int bn = blockIdx.x;
    __shared__ float ems[12];
    int t = threadIdx.x;
    if (t < 12) {
        const float* xp = x + ((long)bn*12 + t)*64;
        float s = 0;
        #pragma unroll 8
        for (int c = 0; c < 64; c++) s += xp[c];
        ems[t] = s * (1.f/64.f);
        em[bn*12 + t] = ems[t];
    }
    __syncthreads();
    if (t < 12) {
        float s3 = 0, s4 = 0;
        #pragma unroll
        for (int tt = 0; tt < 12; tt++){ s3 += ems[tt]*w3[tt*12+t]; s4 += ems[tt]*w4[tt*12+t]; }
        u3[bn*12+t] = s3; u4[bn*12+t] = s4;
    }
}
__global__ void k_S(const float* u3, const float* u4, float* S3, float* S4, float* C34){
    int b = blockIdx.x, tid = threadIdx.x;
    int o = tid/12, p = tid%12;
    float c = 0, s3 = 0, s4 = 0;
    for (int n = 0; n < N_; n++){
        float a = u3[(b*N_+n)*12+o], r = u4[(b*N_+n)*12+p];
        c += a*r;
        if (p == 0) s3 += a;
        if (o == 0) s4 += r;
    }
    C34[b*144+tid] = c;
    if (p == 0) S3[b*12+o] = s3;
    if (o == 0) S4[b*12+p] = s4;
}
__global__ void k_attE(const float* u3, const float* u4, const float* S3, const float* S4,
                       const float* C34, const float* P, const float* em,
                       const float* alphaE, float* attE, float* coefE){
    int bn = blockIdx.x; int b = bn / N_; int n = bn % N_;
    int tid = threadIdx.x;
    int o = tid/12, p = tid%12;
    __shared__ float at[144], ems[12];
    float l = (float)N_*u3[bn*12+o]*u4[bn*12+p] + u3[bn*12+o]*S4[b*12+p]
            + S3[b*12+o]*u4[bn*12+p] + C34[b*144+tid];
    float a = sg(l);
    at[tid] = a; attE[(long)bn*144+tid] = a;
    if (tid < 12) ems[tid] = em[bn*12+tid];
    __syncthreads();
    if (tid < 12) {
        float wv = 0;
        #pragma unroll
        for (int oo = 0; oo < 12; oo++) wv += ems[oo]*at[oo*12+tid];
        coefE[bn*12+tid] = 0.5f*sg(alphaE[n])*P[bn*12+tid] + wv;
    }
}
__global__ void k_base(const float* coefE, const float* fw, float* base){
    int b = blockIdx.y, t = blockIdx.x, c = threadIdx.x;
    float s = 0;
    #pragma unroll 4
    for (int n = 0; n < N_; n++) s += fw[n*64+c] * coefE[(b*N_+n)*12+t];
    base[(b*12+t)*64+c] = s;
}
__global__ void k_R(const float* attE, const float* fw, float* R){
    int b = blockIdx.y, tp = blockIdx.x, c = threadIdx.x;
    float s = 0;
    #pragma unroll 4
    for (int n = 0; n < N_; n++) s += attE[((long)b*N_+n)*144+tp] * fw[n*64+c];
    R[((long)b*144+tp)*64+c] = s;
}
__global__ void k_g0(const float* fw, const float* alphaE, const float* rs, float* g0){
    int c = threadIdx.x; float s = 0;
    for (int n = 0; n < N_; n++) s += fw[n*64+c]*sg(alphaE[n])*rs[n];
    g0[c] = 0.5f*s;
}
__global__ void k_al(const float* x, const float* w3, const float* w4,
                     float* al, float* ar){
    __shared__ float w3s[144], w4s[144];
    int bn = blockIdx.x, c = threadIdx.x;
    for (int i = c; i < 144; i += 64){ w3s[i] = w3[i]; w4s[i] = w4[i]; }
    __syncthreads();
    float xr[12];
    const float* xp = x + (long)bn*768 + c;
    #pragma unroll
    for (int t = 0; t < 12; t++) xr[t] = xp[t*64];
    #pragma unroll
    for (int o = 0; o < 12; o++){
        float a = 0, r = 0;
        #pragma unroll
        for (int t = 0; t < 12; t++){ a += xr[t]*w3s[t*12+o]; r += xr[t]*w4s[t*12+o]; }
        al[((long)bn*12+o)*64+c] = a; ar[((long)bn*12+o)*64+c] = r;
    }
}
__global__ void k_attN(const float* al, const float* ar, float* attN){
    int c = blockIdx.x, b = blockIdx.y;
    int tid = threadIdx.x;
    int o = tid/12, p = tid%12;
    __shared__ float alc[32*12], arc[32*12];
    float acc = 0;
    for (int n0 = 0; n0 < N_; n0 += 32){
        int cnt = min(32, N_ - n0);
        __syncthreads();
        for (int i = tid; i < cnt*12; i += 144){
            int nn = i/12, oo = i%12;
            long base = (((long)b*N_ + n0 + nn)*12 + oo)*64 + c;
            alc[i] = al[base]; arc[i] = ar[base];
        }
        __syncthreads();
        for (int i = 0; i < cnt; i++) acc += alc[i*12+o]*arc[i*12+p];
    }
    attN[((long)b*64+c)*144 + tid] = sg(acc);
}
__global__ void k_x0n(const float* x, const float* Sn, const float* xw,
                      const float* attN, const float* alphaN, float* x0n){
    int bn = blockIdx.x; int b = bn / N_, n = bn % N_;
    int c = threadIdx.x;
    __shared__ float xs[12][64];
    const float* xp = x + (long)bn*768;
    #pragma unroll
    for (int t = 0; t < 12; t++) xs[t][c] = xp[t*64+c];
    __syncthreads();
    float aN = 0.5f*sg(alphaN[n]);
    const float* an = attN + ((long)b*64+c)*144;
    #pragma unroll
    for (int o = 0; o < 12; o++){
        float tn = 0;
        #pragma unroll
        for (int p = 0; p < 12; p++) tn += an[o*12+p]*xs[p][c];
        long idx = (long)bn*768 + o*64 + c;
        x0n[idx] = aN*Sn[idx] + tn + xw[idx] - xs[o][c];
    }
}
__global__ void k_mhsa(const float* qkv, float* z0, float* z){
    int h = blockIdx.x, b = blockIdx.y;
    __shared__ __align__(16) float Ks[N_*DK_];
    __shared__ __align__(16) float Vs[N_*DV_];
    int tid = threadIdx.x;
    for (int i = tid; i < N_*DK_; i += 256){
        int n = i/DK_, d = i%DK_;
        Ks[i] = qkv[((long)b*N_+n)*1792 + 768 + h*DK_ + d];
    }
    for (int i = tid; i < N_*DV_; i += 256){
        int n = i/DV_, d = i%DV_;
        Vs[i] = qkv[((long)b*N_+n)*1792 + 1536 + h*DV_ + d];
    }
    __syncthreads();
    const float4* K4 = (const float4*)Ks;
    const float4* V4 = (const float4*)Vs;
    for (int r = 0; r < 2; r++){
        int n = tid + r*256;
        if (n >= N_) break;
        float qr[DK_];
        const float* qp = qkv + ((long)b*N_+n)*1792 + h*DK_;
        #pragma unroll
        for (int d = 0; d < DK_; d++) qr[d] = qp[d];
        float mmax = -1e30f, l = 0.f, acc[DV_] = {};
        for (int m = 0; m < N_; m++){
            float s = 0;
            #pragma unroll
            for (int i = 0; i < 6; i++){
                float4 kv = K4[m*6+i];
                s += qr[i*4+0]*kv.x + qr[i*4+1]*kv.y + qr[i*4+2]*kv.z + qr[i*4+3]*kv.w;
            }
            s *= NORM_;
            float nm = fmaxf(mmax, s);
            float e0 = __expf(mmax - nm);
            float e1 = __expf(s - nm);
            l = l*e0 + e1;
            float4 v0 = V4[m*2+0], v1 = V4[m*2+1];
            acc[0] = acc[0]*e0 + e1*v0.x; acc[1] = acc[1]*e0 + e1*v0.y;
            acc[2] = acc[2]*e0 + e1*v0.z; acc[3] = acc[3]*e0 + e1*v0.w;
            acc[4] = acc[4]*e0 + e1*v1.x; acc[5] = acc[5]*e0 + e1*v1.y;
            acc[6] = acc[6]*e0 + e1*v1.z; acc[7] = acc[7]*e0 + e1*v1.w;
            mmax = nm;
        }
        float inv = 1.f/l;
        #pragma unroll
        for (int j = 0; j < DV_; j++){
            int flat = h*DV_ + j;
            int g = flat >> 6, c = flat & 63;
            long idx = (((long)g*B_+b)*N_+n)*64 + c;
            float val = acc[j]*inv;
            z0[idx] = val; z[idx] = val;
        }
    }
}
__global__ void k_att3(const float* z, const float* w31, const float* w41, float* att3){
    int gb = blockIdx.x, c = threadIdx.x;
    float s = 0;
    const float* zp = z + (long)gb*N_*64 + c;
    #pragma unroll 4
    for (int n = 0; n < N_; n++){ float v = zp[n*64]; s += v*v; }
    att3[gb*64+c] = sg(w31[0]*w41[0]*s);
}
__global__ void k_step(const float* zin, const float* Sz, const float* zw,
                       const float* z0, const float* att3, const float* alpha3,
                       float* zout, float* x1s, int step){
    long idx = (long)blockIdx.x*256 + threadIdx.x;
    if (idx >= G4) return;
    int c = idx & 63;
    long r = idx >> 6;
    int n = r % N_; long r2 = r / N_;
    int b = r2 % B_; int g = (int)(r2 / B_);
    float zv = zin[idx];
    float out = 0.5f*sg(alpha3[g*N_+n])*Sz[idx] + att3[(g*B_+b)*64+c]*zv
              + zw[idx] + z0[idx] - 2.f*zv;
    zout[idx] = out;
    x1s[(((long)b*N_+n)*12 + step*4 + g)*64 + c] = out;
}
__global__ void k_clip(const float* x1s, const float* x0n, const float* clip, float* x1c){
    long idx = (long)blockIdx.x*256 + threadIdx.x;
    if (idx >= ELT) return;
    float hi = x0n[idx] + clip[0], lo = x0n[idx] - clip[0];
    float v = x1s[idx];
    if (hi - v < 0.f) v = hi;
    if (lo - v > 0.f) v = lo;
    x1c[idx] = v;
}
__global__ void k_xe(const float* em, const float* base, const float* g0,
                     const float* R, const float* fb, float* xe){
    int bm = blockIdx.x; int b = bm / N_;
    int c = threadIdx.x;
    float emr[12];
    #pragma unroll
    for (int t = 0; t < 12; t++) emr[t] = em[bm*12+t];
    float g0c = g0[c], fbc = fb[c];
    #pragma unroll
    for (int t = 0; t < 12; t++){
        float acc = base[(b*12+t)*64+c] + emr[t]*g0c + fbc;
        #pragma unroll
        for (int tp = 0; tp < 12; tp++)
            acc += emr[tp]*R[((long)b*144 + tp*12 + t)*64 + c];
        xe[((long)bm*12+t)*64+c] = acc;
    }
}
__global__ void k_final1(const float* xg, const float* xl, const float* xe,
                         const float* res, float* z1){
    long idx = (long)blockIdx.x*256 + threadIdx.x;
    if (idx >= ELT) return;
    float a = xg[idx], b = xl[idx], e = xe[idx];
    float sa = sg(a), sb = sg(b), se = sg(e);
    z1[idx] = (a*(sb+se) + b*(se+sa) + e*(sb+sa) + res[idx]) * (1.f/6.f);
}
__global__ void k_final2(const float* t1, const float* t2, float* out){
    long idx = (long)blockIdx.x*256 + threadIdx.x;
    if (idx >= ELT) return;
    out[idx] = fmaxf(sg(t1[idx]) + t2[idx], 0.f);
}

// ---------------- host ----------------
static void g128(const float* A, int lda, long sA, const float* B, int ldb, long sB,
                 float* C, int ldc, long sC, int M, int K, int cols,
                 const float* bias, int batch){
    if (cols % 128 == 0) {
        dim3 g(cols/128, (M+127)/128, batch);
        k_gemm128<128><<<g, 256>>>(A, lda, sA, B, ldb, sB, C, ldc, sC, M, K, cols, bias);
    } else {
        dim3 g(cols/64, (M+127)/128, batch);
        k_gemm128<64><<<g, 256>>>(A, lda, sA, B, ldb, sB, C, ldc, sC, M, K, cols, bias);
    }
}
static void gemmF(const float* A, int lda, long sA, const float* B, int ldb, long sB,
                  float* C, int ldc, long sC, int M, int K, int cols,
                  const float* bias, int batch){
    dim3 g((cols+63)/64, (M+63)/64, batch);
    k_gemm<<<g, 256>>>(A, lda, sA, B, ldb, sB, C, ldc, sC, M, K, cols, bias);
}

extern "C" void kernel_launch(void* const* d_in, const int* in_sizes, int n_in,
                              void* d_out, int out_size){
    const float* x      = (const float*)d_in[0];
    const float* adj    = (const float*)d_in[1];
    const float* mask   = (const float*)d_in[2];
    const float* w3_12  = (const float*)d_in[3];
    const float* w4_12  = (const float*)d_in[4];
    const float* w3_1   = (const float*)d_in[5];
    const float* w4_1   = (const float*)d_in[6];
    const float* alphaN = (const float*)d_in[7];
    const float* w_n11  = (const float*)d_in[8];
    const float* d_n11  = (const float*)d_in[9];
    const float* alphaE = (const float*)d_in[10];
    const float* alpha3 = (const float*)d_in[11];
    const float* w_3    = (const float*)d_in[12];
    const float* d_3    = (const float*)d_in[13];
    const float* wq     = (const float*)d_in[14];
    const float* bq     = (const float*)d_in[15];
    const float* wk     = (const float*)d_in[16];
    const float* bk     = (const float*)d_in[17];
    const float* wv     = (const float*)d_in[18];
    const float* bv     = (const float*)d_in[19];
    const float* fc1w   = (const float*)d_in[20];
    const float* fc1b   = (const float*)d_in[21];
    const float* fc2w   = (const float*)d_in[22];
    const float* fc2b   = (const float*)d_in[23];
    const float* fcew   = (const float*)d_in[24];
    const float* fceb   = (const float*)d_in[25];
    const float* clip   = (const float*)d_in[26];
    float* out = (float*)d_out;

    float* S;
    cudaGetSymbolAddress((void**)&S, g_s);
    float *A = S+O_A, *RS = S+O_RS, *W = S+O_W, *EM = S+O_EM, *U3 = S+O_U3, *U4 = S+O_U4;
    float *P = S+O_P, *S3 = S+O_S3, *S4 = S+O_S4, *C34 = S+O_C34, *ATTE = S+O_ATTE;
    float *COEFE = S+O_COEFE, *BASE = S+O_BASE, *R = S+O_R, *G0 = S+O_G0, *SN = S+O_SN;
    float *AL = S+O_AL, *AR = S+O_AR, *ATTN = S+O_ATTN, *XW = S+O_XW, *X0N = S+O_X0N;
    float *QKV = S+O_QKV, *Z0 = S+O_Z0, *Z = S+O_Z;
    float *SZ = S+O_SZ, *ZW = S+O_ZW, *ATT3 = S+O_ATT3, *X1S = S+O_X1S, *X1C = S+O_X1C;
    float *XG = S+O_XG, *XL = S+O_XL, *XE = S+O_XE, *Z1 = S+O_Z1, *T1 = S+O_T1, *T2 = S+O_T2;

    k_A<<<(N_*N_+255)/256, 256>>>(adj, mask, A);
    k_rs<<<(N_+31)/32, 32>>>(A, RS);
    k_W<<<5, 1024>>>(w_n11, d_n11, w_3, d_3, W);
    k_em<<<B_*N_, 32>>>(x, w3_12, w4_12, EM, U3, U4);
    k_S<<<B_, 144>>>(U3, U4, S3, S4, C34);
    gemmF(A, N_, 0, EM, 12, (long)N_*12, P, 12, (long)N_*12, N_, N_, 12, nullptr, B_);
    k_attE<<<B_*N_, 144>>>(U3, U4, S3, S4, C34, P, EM, alphaE, ATTE, COEFE);
    k_base<<<dim3(12, B_), 64>>>(COEFE, fcew, BASE);
    k_R<<<dim3(144, B_), 64>>>(ATTE, fcew, R);
    k_g0<<<1, 64>>>(fcew, alphaE, RS, G0);
    g128(A, N_, 0, x, TC_, (long)N_*TC_, SN, TC_, (long)N_*TC_, N_, N_, TC_, nullptr, B_);
    g128(x, 64, 0, W, 64, 0, XW, 64, 0, B_*N_*T_, 64, 64, nullptr, 1);
    k_al<<<B_*N_, 64>>>(x, w3_12, w4_12, AL, AR);
    k_attN<<<dim3(64, B_), 144>>>(AL, AR, ATTN);
    k_x0n<<<B_*N_, 64>>>(x, SN, XW, ATTN, alphaN, X0N);
    k_qkv_mma<<<dim3(28, 39), 256>>>(x, wq, wk, wv, bq, bk, bv, QKV);
    k_mhsa<<<dim3(NH_, B_), 256>>>(QKV, Z0, Z);
    for (int step = 0; step < 3; step++){
        g128(A, N_, 0, Z, 64, (long)N_*64, SZ, 64, (long)N_*64, N_, N_, 64, nullptr, 64);
        g128(Z, 64, 16L*N_*64, W + 4096, 64, 4096, ZW, 64, 16L*N_*64, B_*N_, 64, 64, nullptr, 4);
        k_att3<<<64, 64>>>(Z, w3_1, w4_1, ATT3);
        k_step<<<(int)((G4+255)/256), 256>>>(Z, SZ, ZW, Z0, ATT3, alpha3, Z, X1S, step);
    }
    k_clip<<<(int)((ELT+255)/256), 256>>>(X1S, X0N, clip, X1C);
    g128(X1C, 64, 0, fc1w, 64, 0, XG, 64, 0, B_*N_*T_, 64, 64, fc1b, 1);
    g128(X0N, 64, 0, fc1w, 64, 0, XL, 64, 0, B_*N_*T_, 64, 64, fc1b, 1);
    k_xe<<<B_*N_, 64>>>(EM, BASE, G0, R, fceb, XE);
    k_final1<<<(int)((ELT+255)/256), 256>>>(XG, XL, XE, x, Z1);
    g128(x, 64, 0, fc2w, 64, 0, T1, 64, 0, B_*N_*T_, 64, 64, fc2b, 1);
    g128(Z1, 64, 0, fc2w, 64, 0, T2, 64, 0, B_*N_*T_, 64, 64, fc2b, 1);
    k_final2<<<(int)((ELT+255)/256), 256>>>(T1, T2, out);
}